// round 2
// baseline (speedup 1.0000x reference)
#include <cuda_runtime.h>

// DecoderSphere: out[b,t] = head( 5x resnet( p@Wp + b + cf ) ), cf = sphere bilinear gather.
// B=16, T=65536, D=32. Fully fused, one thread per point, f32x2 packed math.

#define BATCH 16
#define TPTS  65536
#define DIM   32
#define NPTS  (BATCH * TPTS)
#define TPB   128

typedef unsigned long long ull;

__device__ __forceinline__ ull pack2(float lo, float hi) {
    ull r; asm("mov.b64 %0, {%1, %2};" : "=l"(r) : "f"(lo), "f"(hi)); return r;
}
__device__ __forceinline__ void unpack2(ull v, float &lo, float &hi) {
    asm("mov.b64 {%0, %1}, %2;" : "=f"(lo), "=f"(hi) : "l"(v));
}
__device__ __forceinline__ ull fma2(ull a, ull b, ull c) {
    ull r; asm("fma.rn.f32x2 %0, %1, %2, %3;" : "=l"(r) : "l"(a), "l"(b), "l"(c)); return r;
}
__device__ __forceinline__ ull add2(ull a, ull b) {
    ull r; asm("add.rn.f32x2 %0, %1, %2;" : "=l"(r) : "l"(a), "l"(b)); return r;
}
__device__ __forceinline__ ull mul2(ull a, ull b) {
    ull r; asm("mul.rn.f32x2 %0, %1, %2;" : "=l"(r) : "l"(a), "l"(b)); return r;
}

// Shared weight arena layout (floats)
#define OFF_FCPW 0          // [3][32]   = 96
#define OFF_FCPB 96         // [32]
#define OFF_W0   128        // [5][32][32] = 5120
#define OFF_B0   5248       // [5][32] = 160
#define OFF_W1   5408       // [5][32][32] = 5120
#define OFF_B1   10528      // [5][32] = 160
#define OFF_FOW  10688      // [32]
#define OFF_FOB  10720      // [1]
#define S_TOTAL  10752

__global__ void __launch_bounds__(TPB)
decoder_sphere_kernel(const float* __restrict__ p,
                      const float* __restrict__ c,
                      const float* __restrict__ fcpw,
                      const float* __restrict__ fcpb,
                      const float* __restrict__ w0,
                      const float* __restrict__ b0,
                      const float* __restrict__ w1,
                      const float* __restrict__ b1,
                      const float* __restrict__ fow,
                      const float* __restrict__ fob,
                      float* __restrict__ out)
{
    __shared__ __align__(16) float s[S_TOTAL];

    const int tid = threadIdx.x;
    // Stage all weights into SMEM (broadcast-read later; conflict-free)
    for (int idx = tid; idx < 96;   idx += TPB) s[OFF_FCPW + idx] = fcpw[idx];
    for (int idx = tid; idx < 32;   idx += TPB) s[OFF_FCPB + idx] = fcpb[idx];
    for (int idx = tid; idx < 5120; idx += TPB) s[OFF_W0   + idx] = w0[idx];
    for (int idx = tid; idx < 160;  idx += TPB) s[OFF_B0   + idx] = b0[idx];
    for (int idx = tid; idx < 5120; idx += TPB) s[OFF_W1   + idx] = w1[idx];
    for (int idx = tid; idx < 160;  idx += TPB) s[OFF_B1   + idx] = b1[idx];
    for (int idx = tid; idx < 32;   idx += TPB) s[OFF_FOW  + idx] = fow[idx];
    if (tid == 0) s[OFF_FOB] = fob[0];
    __syncthreads();

    const int i  = blockIdx.x * TPB + tid;   // grid sized exactly NPTS/TPB
    const int bb = i >> 16;                  // T = 65536

    const float* pp = p + (size_t)i * 3;
    const float px = pp[0], py = pp[1], pz = pp[2];

    // ---- sphere bilinear interp indices (replicates reference fp32 math) ----
    const float PI_F = 3.1415927410125732f;
    float lat = 90.0f - (atan2f(pz, sqrtf(px * px + py * py)) * 180.0f) / PI_F;
    float mer = fmodf(360.0f + (atan2f(py, px) * 180.0f) / PI_F, 360.0f);
    float y_grid = floorf(lat / 2.8125f);   // 180/64
    float x_grid = floorf(mer / 5.625f);    // 360/64

    float xlf = x_grid - 1.0f; xlf -= 64.0f * floorf(xlf * 0.015625f);  // (x-1) mod 64
    float xrf = x_grid + 1.0f; xrf -= 64.0f * floorf(xrf * 0.015625f);  // (x+1) mod 64
    float ylf = y_grid - 1.0f; ylf -= floorf(ylf * 0.015625f);          // y-1 - floor((y-1)/64)
    float yhf = y_grid + 1.0f; yhf -= floorf(yhf * 0.015625f);          // y+1 - floor((y+1)/64)

    const float dx = xrf - x_grid;
    const float dy = yhf - y_grid;
    const int xl = (int)xlf, xr = (int)xrf, yl = (int)ylf, yh = (int)yhf;

    // NOTE reference quirk: gather(grid, x_idx, y_idx) -> grid[x][y][:]
    const float* gb = c + (size_t)bb * (64 * 64 * DIM);
    const float4* F11 = (const float4*)(gb + (size_t)(xl * 64 + yl) * DIM);
    const float4* F12 = (const float4*)(gb + (size_t)(xr * 64 + yl) * DIM);
    const float4* F21 = (const float4*)(gb + (size_t)(xl * 64 + yh) * DIM);
    const float4* F22 = (const float4*)(gb + (size_t)(xr * 64 + yh) * DIM);

    const float w11 = dx * dy, w12 = (1.0f - dx) * dy;
    const float w21 = dx * (1.0f - dy), w22 = (1.0f - dx) * (1.0f - dy);
    const ull W11 = pack2(w11, w11), W12 = pack2(w12, w12);
    const ull W21 = pack2(w21, w21), W22 = pack2(w22, w22);

    ull cf[16];
    #pragma unroll
    for (int q = 0; q < 8; ++q) {
        float4 a  = F11[q];
        float4 b4 = F12[q];
        float4 c4 = F21[q];
        float4 d4 = F22[q];
        ull acc = mul2(pack2(a.x, a.y), W11);
        acc = fma2(pack2(b4.x, b4.y), W12, acc);
        acc = fma2(pack2(c4.x, c4.y), W21, acc);
        acc = fma2(pack2(d4.x, d4.y), W22, acc);
        cf[2 * q] = acc;
        acc = mul2(pack2(a.z, a.w), W11);
        acc = fma2(pack2(b4.z, b4.w), W12, acc);
        acc = fma2(pack2(c4.z, c4.w), W21, acc);
        acc = fma2(pack2(d4.z, d4.w), W22, acc);
        cf[2 * q + 1] = acc;
    }

    // ---- net = p @ fc_p_w + fc_p_b ----
    const ull PX = pack2(px, px), PY = pack2(py, py), PZ = pack2(pz, pz);
    const ull* fpw0 = (const ull*)&s[OFF_FCPW + 0];
    const ull* fpw1 = (const ull*)&s[OFF_FCPW + 32];
    const ull* fpw2 = (const ull*)&s[OFF_FCPW + 64];
    const ull* fpb  = (const ull*)&s[OFF_FCPB];

    ull net[16];
    #pragma unroll
    for (int k = 0; k < 16; ++k) {
        ull a = fma2(PX, fpw0[k], fpb[k]);
        a = fma2(PY, fpw1[k], a);
        net[k] = fma2(PZ, fpw2[k], a);
    }

    // ---- 5 resnet blocks ----
    #pragma unroll
    for (int l = 0; l < 5; ++l) {
        const float* W0 = &s[OFF_W0 + l * 1024];
        const float* W1 = &s[OFF_W1 + l * 1024];
        const ull* B0 = (const ull*)&s[OFF_B0 + l * 32];
        const ull* B1 = (const ull*)&s[OFF_B1 + l * 32];

        #pragma unroll
        for (int k = 0; k < 16; ++k) net[k] = add2(net[k], cf[k]);

        // h = relu( relu(net) @ w0 + b0 )
        ull h[16];
        #pragma unroll
        for (int k = 0; k < 16; ++k) h[k] = B0[k];

        #pragma unroll
        for (int k = 0; k < 16; ++k) {
            float lo, hi; unpack2(net[k], lo, hi);
            lo = fmaxf(lo, 0.0f); hi = fmaxf(hi, 0.0f);
            const ull RL = pack2(lo, lo), RH = pack2(hi, hi);
            const float4* r0 = (const float4*)&W0[(2 * k) * 32];
            const float4* r1 = (const float4*)&W0[(2 * k + 1) * 32];
            #pragma unroll
            for (int q = 0; q < 8; ++q) {
                float4 wa = r0[q];
                h[2 * q]     = fma2(RL, pack2(wa.x, wa.y), h[2 * q]);
                h[2 * q + 1] = fma2(RL, pack2(wa.z, wa.w), h[2 * q + 1]);
            }
            #pragma unroll
            for (int q = 0; q < 8; ++q) {
                float4 wb = r1[q];
                h[2 * q]     = fma2(RH, pack2(wb.x, wb.y), h[2 * q]);
                h[2 * q + 1] = fma2(RH, pack2(wb.z, wb.w), h[2 * q + 1]);
            }
        }

        // net = net + h(relu'd) @ w1 + b1
        #pragma unroll
        for (int k = 0; k < 16; ++k) net[k] = add2(net[k], B1[k]);

        #pragma unroll
        for (int k = 0; k < 16; ++k) {
            float lo, hi; unpack2(h[k], lo, hi);
            lo = fmaxf(lo, 0.0f); hi = fmaxf(hi, 0.0f);
            const ull HL = pack2(lo, lo), HH = pack2(hi, hi);
            const float4* r0 = (const float4*)&W1[(2 * k) * 32];
            const float4* r1 = (const float4*)&W1[(2 * k + 1) * 32];
            #pragma unroll
            for (int q = 0; q < 8; ++q) {
                float4 wa = r0[q];
                net[2 * q]     = fma2(HL, pack2(wa.x, wa.y), net[2 * q]);
                net[2 * q + 1] = fma2(HL, pack2(wa.z, wa.w), net[2 * q + 1]);
            }
            #pragma unroll
            for (int q = 0; q < 8; ++q) {
                float4 wb = r1[q];
                net[2 * q]     = fma2(HH, pack2(wb.x, wb.y), net[2 * q]);
                net[2 * q + 1] = fma2(HH, pack2(wb.z, wb.w), net[2 * q + 1]);
            }
        }
    }

    // ---- out = relu(net) @ fc_out_w + fc_out_b ----
    float acc = s[OFF_FOB];
    const float* FW = &s[OFF_FOW];
    #pragma unroll
    for (int k = 0; k < 16; ++k) {
        float lo, hi; unpack2(net[k], lo, hi);
        acc = fmaf(fmaxf(lo, 0.0f), FW[2 * k], acc);
        acc = fmaf(fmaxf(hi, 0.0f), FW[2 * k + 1], acc);
    }
    out[i] = acc;
}

extern "C" void kernel_launch(void* const* d_in, const int* in_sizes, int n_in,
                              void* d_out, int out_size)
{
    // metadata order: p, z, c, C_mat, fc_p_w, fc_p_b, w0, b0, w1, b1, fc_out_w, fc_out_b
    const float* p    = (const float*)d_in[0];
    const float* c    = (const float*)d_in[2];
    const float* fcpw = (const float*)d_in[4];
    const float* fcpb = (const float*)d_in[5];
    const float* w0   = (const float*)d_in[6];
    const float* b0   = (const float*)d_in[7];
    const float* w1   = (const float*)d_in[8];
    const float* b1   = (const float*)d_in[9];
    const float* fow  = (const float*)d_in[10];
    const float* fob  = (const float*)d_in[11];
    float* out = (float*)d_out;

    decoder_sphere_kernel<<<NPTS / TPB, TPB>>>(p, c, fcpw, fcpb, w0, b0, w1, b1, fow, fob, out);
}